// round 5
// baseline (speedup 1.0000x reference)
#include <cuda_runtime.h>

typedef unsigned long long u64;

// ---------- packed f32x2 helpers (Blackwell sm_100+) ----------
__device__ __forceinline__ u64 pk2(float a, float b) {
    u64 r; asm("mov.b64 %0,{%1,%2};" : "=l"(r) : "f"(a), "f"(b)); return r;
}
__device__ __forceinline__ float2 upk(u64 v) {
    float2 r; asm("mov.b64 {%0,%1},%2;" : "=f"(r.x), "=f"(r.y) : "l"(v)); return r;
}
__device__ __forceinline__ u64 fma2(u64 a, u64 b, u64 c) {
    u64 d; asm("fma.rn.f32x2 %0,%1,%2,%3;" : "=l"(d) : "l"(a), "l"(b), "l"(c)); return d;
}
__device__ __forceinline__ u64 mul2(u64 a, u64 b) {
    u64 d; asm("mul.rn.f32x2 %0,%1,%2;" : "=l"(d) : "l"(a), "l"(b)); return d;
}
__device__ __forceinline__ u64 add2(u64 a, u64 b) {
    u64 d; asm("add.rn.f32x2 %0,%1,%2;" : "=l"(d) : "l"(a), "l"(b)); return d;
}
__device__ __forceinline__ u64 neg2(u64 a) {
    u64 r; asm("xor.b64 %0,%1,%2;" : "=l"(r) : "l"(a), "l"(0x8000000080000000ULL));
    return r;
}
__device__ __forceinline__ u64 sub2(u64 a, u64 b) { return add2(a, neg2(b)); }

// Per-line computation. Lane 0 = u-stream (qubits 0,1), lane 1 = v-stream
// (qubits 2,3). kA/kB: layer-1 gate constants; oA/oB: observables.
__device__ __forceinline__ float4 line_compute(
    float4 F0, float4 F1, float4 F2,
    const u64* __restrict__ kA, const u64* __restrict__ kB,
    const u64* __restrict__ oA, const u64* __restrict__ oB)
{
    const float PIH = 1.57079632679489662f;
    float sb0, cb0, sz0, cz0, sb1, cb1, sz1, cz1;
    float sb2, cb2, sz2, cz2, sb3, cb3, sz3, cz3;
    __sincosf(PIH * F0.y, &sb0, &cb0);  __sincosf(PIH * F0.z, &sz0, &cz0);
    __sincosf(PIH * F1.x, &sb1, &cb1);  __sincosf(PIH * F1.y, &sz1, &cz1);
    __sincosf(PIH * F1.w, &sb2, &cb2);  __sincosf(PIH * F2.x, &sz2, &cz2);
    __sincosf(PIH * F2.z, &sb3, &cb3);  __sincosf(PIH * F2.w, &sz3, &cz3);

    // pack: stream A lanes [q0,q2], stream B lanes [q1,q3]
    u64 cbA = pk2(cb0, cb2), sbA = pk2(sb0, sb2);
    u64 czA = pk2(cz0, cz2), szA = pk2(sz0, sz2);
    u64 cbB = pk2(cb1, cb3), sbB = pk2(sb1, sb3);
    u64 czB = pk2(cz1, cz3), szB = pk2(sz1, sz3);

    // encoding vector (u0r, -t0, u1r, +t1) then layer-1 gate, signs folded
    u64 a0r, a0i, a1r, a1i;
    {
        u64 u0r = mul2(cbA, czA), t0 = mul2(cbA, szA);
        u64 u1r = mul2(sbA, czA), t1 = mul2(sbA, szA);
        u64 t0n = neg2(t0);
        a0r = fma2(kA[3], t1, fma2(kA[2], u1r, fma2(kA[1], t0,  mul2(kA[0], u0r))));
        a0i = fma2(kA[2], t1, fma2(kA[4], u1r, fma2(kA[0], t0n, mul2(kA[1], u0r))));
        a1r = fma2(kA[8], t1, fma2(kA[7], u1r, fma2(kA[6], t0,  mul2(kA[5], u0r))));
        a1i = fma2(kA[7], t1, fma2(kA[9], u1r, fma2(kA[5], t0n, mul2(kA[6], u0r))));
    }
    u64 b0r, b0i, b1r, b1i;
    {
        u64 u0r = mul2(cbB, czB), t0 = mul2(cbB, szB);
        u64 u1r = mul2(sbB, czB), t1 = mul2(sbB, szB);
        u64 t0n = neg2(t0);
        b0r = fma2(kB[3], t1, fma2(kB[2], u1r, fma2(kB[1], t0,  mul2(kB[0], u0r))));
        b0i = fma2(kB[2], t1, fma2(kB[4], u1r, fma2(kB[0], t0n, mul2(kB[1], u0r))));
        b1r = fma2(kB[8], t1, fma2(kB[7], u1r, fma2(kB[6], t0,  mul2(kB[5], u0r))));
        b1i = fma2(kB[7], t1, fma2(kB[9], u1r, fma2(kB[5], t0n, mul2(kB[6], u0r))));
    }

    // pair product p = A (x) B, with CZ(0,1)/CZ(2,3) folded (p3 negated).
    u64 nb0i = neg2(b0i), nb1i = neg2(b1i);
    u64 p0r = fma2(a0i, nb0i, mul2(a0r, b0r)), p0i = fma2(a0i, b0r, mul2(a0r, b0i));
    u64 p1r = fma2(a0i, nb1i, mul2(a0r, b1r)), p1i = fma2(a0i, b1r, mul2(a0r, b1i));
    u64 p2r = fma2(a1i, nb0i, mul2(a1r, b0r)), p2i = fma2(a1i, b0r, mul2(a1r, b0i));
    u64 p3r = neg2(fma2(a1i, nb1i, mul2(a1r, b1r)));
    u64 p3i = neg2(fma2(a1i, b1r, mul2(a1r, b1i)));

    // probabilities and diagonal-Z combos (pair norms are 1)
    u64 P0 = fma2(p0i, p0i, mul2(p0r, p0r));
    u64 P1 = fma2(p1i, p1i, mul2(p1r, p1r));
    u64 P2 = fma2(p2i, p2i, mul2(p2r, p2r));
    u64 P3 = fma2(p3i, p3i, mul2(p3r, p3r));
    u64 DA = sub2(add2(P0, P1), add2(P2, P3));   // [Du0, Dv2]
    u64 DB = add2(sub2(P0, P1), sub2(P2, P3));   // [Du1, Dv3]

    // cross terms: XA = conj(p0)p2 + conj(p1)p3 -> [X0, X2]
    //              XB = conj(p0)p1 + conj(p2)p3 -> [X1, X3]
    u64 ReXA = fma2(p1i, p3i, fma2(p1r, p3r, fma2(p0i, p2i, mul2(p0r, p2r))));
    u64 ImXA = fma2(p1r, p3i, fma2(p0r, p2i,
               neg2(fma2(p1i, p3r, mul2(p0i, p2r)))));
    u64 ReXB = fma2(p2i, p3i, fma2(p2r, p3r, fma2(p0i, p1i, mul2(p0r, p1r))));
    u64 ImXB = fma2(p2r, p3i, fma2(p0r, p1i,
               neg2(fma2(p2i, p3r, mul2(p0i, p1r)))));

    // observable contraction (CZ(1,2) enters via Du1/Dv2 coupling)
    u64 CA = fma2(oA[2], ImXA, mul2(oA[1], ReXA));  // [cross0, cross2]
    u64 CB = fma2(oB[2], ImXB, mul2(oB[1], ReXB));  // [cross1, cross3]
    u64 GA = mul2(oA[0], DA);                       // [a0*Du0, a2*Dv2]
    u64 GB = mul2(oB[0], DB);                       // [a1*Du1, a3*Dv3]

    float2 dA = upk(DA), dB = upk(DB);
    float2 ca = upk(CA), cb_ = upk(CB), ga = upk(GA), gb = upk(GB);
    float z0 = ga.x + ca.x;
    float z1 = fmaf(cb_.x, dA.y, gb.x);   // cross1 * Dv2
    float z2 = fmaf(ca.y, dB.x, ga.y);    // cross2 * Du1
    float z3 = gb.y + cb_.y;
    return make_float4(z0, z1, z2, z3);
}

// Two lines per thread: two independent dependency chains for ILP; the
// shared-memory constant loads and addressing amortize over both.
__global__ __launch_bounds__(128)
void qcnn_kernel(const float* __restrict__ x, const float* __restrict__ w,
                 float* __restrict__ out, int npair) {
    __shared__ u64 sg[2][10];
    __shared__ u64 so[2][3];

    int tid = threadIdx.x;
    int t = blockIdx.x * 128 + tid;

    // Issue all 6 global loads FIRST so DRAM latency overlaps the gate
    // precompute and the barrier below. 2 lines = 24 floats = 6 float4s.
    const float4* xb = (const float4*)(x + (size_t)t * 24);
    float4 E0 = __ldg(xb + 0), E1 = __ldg(xb + 1), E2 = __ldg(xb + 2);
    float4 G0 = __ldg(xb + 3), G1 = __ldg(xb + 4), G2 = __ldg(xb + 5);

    if (tid < 8) {
        int h = tid >> 2, q = tid & 3;
        int s = q & 1, l = q >> 1;     // stream, lane
        const float* wp = w + h * 12 + q * 3;
        float a = wp[0], b = wp[1], g = wp[2];
        float sa, ca, sb, cb, sgg, cgg;
        __sincosf(0.5f * a, &sa, &ca);
        __sincosf(0.5f * b, &sb, &cb);
        __sincosf(0.5f * g, &sgg, &cgg);
        // M = RY * RX
        float m00r = cb * ca, m00i =  sb * sa;
        float m01r = -sb * ca, m01i = -cb * sa;
        float m10r =  sb * ca, m10i = -cb * sa;
        float m11r =  cb * ca, m11i = -sb * sa;
        // U = RZ * M
        float u00r = cgg * m00r + sgg * m00i, u00i = cgg * m00i - sgg * m00r;
        float u01r = cgg * m01r + sgg * m01i, u01i = cgg * m01i - sgg * m01r;
        float u10r = cgg * m10r - sgg * m10i, u10i = cgg * m10i + sgg * m10r;
        float u11r = cgg * m11r - sgg * m11i, u11i = cgg * m11i + sgg * m11r;
        if (h == 0) {
            float* gp = (float*)&sg[s][0];
            gp[0*2+l] = u00r;  gp[1*2+l] = u00i;  gp[2*2+l] = u01r;
            gp[3*2+l] = -u01i; gp[4*2+l] = u01i;
            gp[5*2+l] = u10r;  gp[6*2+l] = u10i;  gp[7*2+l] = u11r;
            gp[8*2+l] = -u11i; gp[9*2+l] = u11i;
        } else {
            // M_q = U^dag Z U = [[a, b+ic],[b-ic, -a]]
            float ma = u00r * u00r + u00i * u00i - u10r * u10r - u10i * u10i;
            float mb = u00r * u01r + u00i * u01i - (u10r * u11r + u10i * u11i);
            float mc = u00r * u01i - u00i * u01r - (u10r * u11i - u10i * u11r);
            float* op = (float*)&so[s][0];
            op[0*2+l] = ma;
            op[1*2+l] = 2.f * mb;
            op[2*2+l] = -2.f * mc;
        }
    }
    __syncthreads();

    if (t >= npair) return;

    float4 zA = line_compute(E0, E1, E2, sg[0], sg[1], so[0], so[1]);
    float4 zB = line_compute(G0, G1, G2, sg[0], sg[1], so[0], so[1]);

    float4* ob = (float4*)(out + (size_t)t * 8);
    ob[0] = zA;   // line 2t
    ob[1] = zB;   // line 2t+1
}

extern "C" void kernel_launch(void* const* d_in, const int* in_sizes, int n_in,
                              void* d_out, int out_size) {
    const float* x = (const float*)d_in[0];   // [128, 2048, 4, 3] f32
    const float* w = (const float*)d_in[1];   // [2, 4, 3] f32
    float* out = (float*)d_out;               // [128, 2048, 4] f32

    int nlines = in_sizes[0] / 12;            // 262144
    int npair = nlines / 2;                   // 131072
    int block = 128;
    int grid = (npair + block - 1) / block;   // 1024
    qcnn_kernel<<<grid, block>>>(x, w, out, npair);
}

// round 6
// speedup vs baseline: 1.3720x; 1.3720x over previous
#include <cuda_runtime.h>

// Bloch-vector formulation. Per line and qubit q:
//   n_enc = (sin(pi x1)cos(pi x2), sin(pi x1)sin(pi x2), cos(pi x1))
//   z_q = r_q . n_enc          (r_q = 3rd row of layer-1 gate Bloch rotation)
//   h_q = s_q . n_enc          (s_q = b_q*row1 - c_q*row2, observable folded)
//   Z0 = a0 z_a + h_a z_b
//   Z1 = a1 z_b + h_b z_a z_c
//   Z2 = a2 z_c + h_c z_b z_d
//   Z3 = a3 z_d + h_d z_c
// (CZ(0,1),CZ(2,3),CZ(1,2) foldings and dropped final-layer CZs / global
// phases verified in earlier rounds; this is an exact algebraic rewrite.)
__global__ __launch_bounds__(256)
void qcnn_kernel(const float* __restrict__ x, const float* __restrict__ w,
                 float* __restrict__ out, int n) {
    // sc[q]   = (r.x, r.y, r.z, a_q)
    // sc[4+q] = (s.x, s.y, s.z, 0)
    __shared__ float4 sc[8];

    int tid = threadIdx.x;
    int t = blockIdx.x * 256 + tid;

    // Issue global loads first: DRAM latency overlaps precompute + barrier.
    const float4* xb = (const float4*)(x + (size_t)t * 12);
    float4 F0 = __ldg(xb + 0), F1 = __ldg(xb + 1), F2 = __ldg(xb + 2);

    if (tid < 4) {
        int q = tid;
        // ---- layer-1 gate U1 = RZ(g)RY(b)RX(a): need u00, u10 only ----
        float a1 = w[q * 3 + 0], b1 = w[q * 3 + 1], g1 = w[q * 3 + 2];
        float sa, ca, sb, cb, sg, cg;
        __sincosf(0.5f * a1, &sa, &ca);
        __sincosf(0.5f * b1, &sb, &cb);
        __sincosf(0.5f * g1, &sg, &cg);
        float m00r = cb * ca, m00i = sb * sa;
        float m10r = sb * ca, m10i = -cb * sa;
        float u00r = cg * m00r + sg * m00i, u00i = cg * m00i - sg * m00r;
        float u10r = cg * m10r - sg * m10i, u10i = cg * m10i + sg * m10r;
        // SU(2) -> quaternion (t,x,y,z): U = tI - i(x sx + y sy + z sz)
        float qt = u00r, qz = -u00i, qy = u10r, qx = -u10i;
        // Bloch rotation rows
        float r1x = 1.f - 2.f * (qy * qy + qz * qz);
        float r1y = 2.f * (qx * qy - qt * qz);
        float r1z = 2.f * (qx * qz + qt * qy);
        float r2x = 2.f * (qx * qy + qt * qz);
        float r2y = 1.f - 2.f * (qx * qx + qz * qz);
        float r2z = 2.f * (qy * qz - qt * qx);
        float r3x = 2.f * (qx * qz - qt * qy);
        float r3y = 2.f * (qy * qz + qt * qx);
        float r3z = 1.f - 2.f * (qx * qx + qy * qy);

        // ---- layer-2 gate U2 -> observable M = U2^dag Z U2 ----
        float a2 = w[12 + q * 3 + 0], b2 = w[12 + q * 3 + 1], g2 = w[12 + q * 3 + 2];
        __sincosf(0.5f * a2, &sa, &ca);
        __sincosf(0.5f * b2, &sb, &cb);
        __sincosf(0.5f * g2, &sg, &cg);
        float n00r = cb * ca, n00i = sb * sa;
        float n01r = -sb * ca, n01i = -cb * sa;
        float n10r = sb * ca, n10i = -cb * sa;
        float n11r = cb * ca, n11i = -sb * sa;
        float v00r = cg * n00r + sg * n00i, v00i = cg * n00i - sg * n00r;
        float v01r = cg * n01r + sg * n01i, v01i = cg * n01i - sg * n01r;
        float v10r = cg * n10r - sg * n10i, v10i = cg * n10i + sg * n10r;
        float v11r = cg * n11r - sg * n11i, v11i = cg * n11i + sg * n11r;
        // M = [[ma, mb+i mc],[mb-i mc, -ma]]
        float ma = v00r * v00r + v00i * v00i - v10r * v10r - v10i * v10i;
        float mb = v00r * v01r + v00i * v01i - (v10r * v11r + v10i * v11i);
        float mc = v00r * v01i - v00i * v01r - (v10r * v11i - v10i * v11r);

        // <M> = ma*z + mb*x - mc*y  ->  s = mb*row1 - mc*row2
        sc[q]     = make_float4(r3x, r3y, r3z, ma);
        sc[4 + q] = make_float4(mb * r1x - mc * r2x,
                                mb * r1y - mc * r2y,
                                mb * r1z - mc * r2z, 0.f);
    }
    __syncthreads();

    if (t >= n) return;

    const float PI = 3.14159265358979323846f;

    float s1, c1, s2, c2;
    // ---- qubit 0 ----
    __sincosf(PI * F0.y, &s1, &c1);
    __sincosf(PI * F0.z, &s2, &c2);
    float xe = s1 * c2, ye = s1 * s2, ze = c1;
    float4 r = sc[0], s = sc[4];
    float za = fmaf(r.z, ze, fmaf(r.y, ye, r.x * xe));
    float ha = fmaf(s.z, ze, fmaf(s.y, ye, s.x * xe));
    float aza = r.w * za;
    // ---- qubit 1 ----
    __sincosf(PI * F1.x, &s1, &c1);
    __sincosf(PI * F1.y, &s2, &c2);
    xe = s1 * c2; ye = s1 * s2; ze = c1;
    r = sc[1]; s = sc[5];
    float zb = fmaf(r.z, ze, fmaf(r.y, ye, r.x * xe));
    float hb = fmaf(s.z, ze, fmaf(s.y, ye, s.x * xe));
    float azb = r.w * zb;
    // ---- qubit 2 ----
    __sincosf(PI * F1.w, &s1, &c1);
    __sincosf(PI * F2.x, &s2, &c2);
    xe = s1 * c2; ye = s1 * s2; ze = c1;
    r = sc[2]; s = sc[6];
    float zc = fmaf(r.z, ze, fmaf(r.y, ye, r.x * xe));
    float hc = fmaf(s.z, ze, fmaf(s.y, ye, s.x * xe));
    float azc = r.w * zc;
    // ---- qubit 3 ----
    __sincosf(PI * F2.z, &s1, &c1);
    __sincosf(PI * F2.w, &s2, &c2);
    xe = s1 * c2; ye = s1 * s2; ze = c1;
    r = sc[3]; s = sc[7];
    float zd = fmaf(r.z, ze, fmaf(r.y, ye, r.x * xe));
    float hd = fmaf(s.z, ze, fmaf(s.y, ye, s.x * xe));
    float azd = r.w * zd;

    float Z0 = fmaf(ha, zb, aza);
    float Z1 = fmaf(hb, za * zc, azb);
    float Z2 = fmaf(hc, zb * zd, azc);
    float Z3 = fmaf(hd, zc, azd);

    ((float4*)out)[t] = make_float4(Z0, Z1, Z2, Z3);
}

extern "C" void kernel_launch(void* const* d_in, const int* in_sizes, int n_in,
                              void* d_out, int out_size) {
    const float* x = (const float*)d_in[0];   // [128, 2048, 4, 3] f32
    const float* w = (const float*)d_in[1];   // [2, 4, 3] f32
    float* out = (float*)d_out;               // [128, 2048, 4] f32

    int nlines = in_sizes[0] / 12;            // 262144
    int block = 256;
    int grid = (nlines + block - 1) / block;  // 1024
    qcnn_kernel<<<grid, block>>>(x, w, out, nlines);
}